// round 14
// baseline (speedup 1.0000x reference)
#include <cuda_runtime.h>
#include <cuda_fp16.h>
#include <cstdint>
#include <math.h>

// ---------------------------------------------------------------------------
// Swin Transformer encoder layer, GB300 round-14:
// fp16 mma.m16n8k16 GEMMs with BK=32 (half the barriers of R13), 4-stage
// cp.async ring (prefetch distance 96 k-elems), 64B-row swizzle.
// ---------------------------------------------------------------------------

#define T_TOK   65536
#define E_DIM   512
#define QKV_N   1536
#define DFF_N   2048
#define NWIN    1024
#define NH_     16
#define HD_     32

// fp32 scratch
__device__ float g_t0[(size_t)T_TOK * E_DIM];
__device__ float g_z[(size_t)T_TOK * E_DIM];
// fp16 scratch
__device__ __half g_x16[(size_t)T_TOK * E_DIM];
__device__ __half g_z16[(size_t)T_TOK * E_DIM];
__device__ __half g_qkv16[(size_t)T_TOK * QKV_N];
__device__ __half g_attn16[(size_t)T_TOK * E_DIM];
__device__ __half g_h16[(size_t)T_TOK * DFF_N];
__device__ __half g_wqkv16[(size_t)QKV_N * E_DIM];
__device__ __half g_wout16[(size_t)E_DIM * E_DIM];
__device__ __half g_w116[(size_t)DFF_N * E_DIM];
__device__ __half g_w216[(size_t)E_DIM * DFF_N];

__device__ __forceinline__ int to_win_row(int m) {
    int b = m >> 14, p = m & 16383;
    int r = p >> 7, c = p & 127;
    int win = (b << 8) + ((r >> 3) << 4) + (c >> 3);
    int n   = ((r & 7) << 3) + (c & 7);
    return (win << 6) + n;
}
__device__ __forceinline__ int from_win_row(int m) {
    int win = m >> 6, n = m & 63;
    int b  = win >> 8, wi = win & 255;
    int wr = wi >> 4,  wc = wi & 15;
    int r = (wr << 3) + (n >> 3);
    int c = (wc << 3) + (n & 7);
    return (b << 14) + (r << 7) + c;
}

__device__ __forceinline__ void mma_f16(float c[4], const uint32_t a[4], const uint32_t b[2]) {
    asm volatile(
        "mma.sync.aligned.m16n8k16.row.col.f32.f16.f16.f32 "
        "{%0,%1,%2,%3},{%4,%5,%6,%7},{%8,%9},{%0,%1,%2,%3};\n"
        : "+f"(c[0]), "+f"(c[1]), "+f"(c[2]), "+f"(c[3])
        : "r"(a[0]), "r"(a[1]), "r"(a[2]), "r"(a[3]), "r"(b[0]), "r"(b[1]));
}

__device__ __forceinline__ void ldsm4(uint32_t& r0, uint32_t& r1, uint32_t& r2, uint32_t& r3,
                                      uint32_t addr) {
    asm volatile("ldmatrix.sync.aligned.m8n8.x4.shared.b16 {%0,%1,%2,%3}, [%4];"
                 : "=r"(r0), "=r"(r1), "=r"(r2), "=r"(r3) : "r"(addr));
}

__device__ __forceinline__ void cpasync16(uint32_t dst, const void* src) {
    asm volatile("cp.async.cg.shared.global [%0], [%1], 16;" :: "r"(dst), "l"(src));
}
__device__ __forceinline__ void cp_commit() {
    asm volatile("cp.async.commit_group;" ::: "memory");
}
template <int N>
__device__ __forceinline__ void cp_wait() {
    asm volatile("cp.async.wait_group %0;" :: "n"(N) : "memory");
}

// ---------------------------------------------------------------------------
// fp32 -> fp16 conversion (4 elems/thread)
// ---------------------------------------------------------------------------
__global__ void cvt_f16_kernel(const float* __restrict__ src, __half* __restrict__ dst, int n) {
    int i = (blockIdx.x * blockDim.x + threadIdx.x) * 4;
    if (i < n) {
        float4 v = *(const float4*)(src + i);
        *(__half2*)(dst + i)     = __floats2half2_rn(v.x, v.y);
        *(__half2*)(dst + i + 2) = __floats2half2_rn(v.z, v.w);
    }
}

// ---------------------------------------------------------------------------
// fp16 NT GEMM: C[m][n] = sum_k A[m][k]*B[n][k] + bias[n]  (fp32 accumulate)
// Block 128x128, BK=32, 128 threads = 4 warps (2m x 2n), warp tile 64x64.
// Smem: k-major 128x32 fp16 tiles (64B rows), swizzle chunk ^= (row>>1)&3;
// 4-stage cp.async ring (distance 3 tiles = 96 k); ldmatrix.x4.b16 reads.
// EPI: 0 bias, 1 bias+relu.  PERM: 0 none, 1 to_win, 2 from_win.
// OUTH: 1 -> __half C, 0 -> float C.
// ---------------------------------------------------------------------------
#define STAGES 4
#define TILE_HB 8192                      // 128 rows * 64 bytes
#define GSM_BYTES (STAGES * TILE_HB * 2)  // 64 KB

template <int EPI, int PERM, int OUTH>
__global__ void __launch_bounds__(128, 2) gemm_f16(
    const __half* __restrict__ A, const __half* __restrict__ B,
    const float* __restrict__ bias, void* __restrict__ Cv,
    int M, int N, int K)
{
    extern __shared__ __align__(128) uint32_t smem[];
    const uint32_t asb = (uint32_t)__cvta_generic_to_shared(smem);
    const uint32_t bsb = asb + STAGES * TILE_HB;

    const int tid  = threadIdx.x;
    const int lane = tid & 31;
    const int warp = tid >> 5;
    const int wr = warp >> 1;        // m half (64 rows)
    const int wc = warp & 1;         // n half (64 cols)
    const int bm = blockIdx.y << 7;
    const int bn = blockIdx.x << 7;

    // loader: thread -> one row (tid), 4 x 16B chunks per matrix
    const int lrow = tid;
    uint32_t soff[4];
#pragma unroll
    for (int j = 0; j < 4; j++)
        soff[j] = (uint32_t)(lrow * 64 + ((j ^ ((lrow >> 1) & 3)) << 4));
    const __half* aP = A + (size_t)(bm + lrow) * K;
    const __half* bP = B + (size_t)(bn + lrow) * K;

    // ldmatrix lane invariants
    const int lm   = (lane & 7) + (((lane >> 3) & 1) << 3);    // A row in 16
    const int ach  = lane >> 4;                                 // A chunk low bit
    const int brow = lane & 7;
    const int bch  = (lane >> 3) & 1;
    const int bnt  = (lane >> 4) & 1;

    float acc[4][8][4];
#pragma unroll
    for (int i = 0; i < 4; i++)
#pragma unroll
        for (int j = 0; j < 8; j++)
#pragma unroll
            for (int v = 0; v < 4; v++) acc[i][j][v] = 0.f;

    const int ntiles = K >> 5;

    // prologue: stages 0..2
#pragma unroll
    for (int s = 0; s < STAGES - 1; s++) {
        const int kk = s << 5;
        const uint32_t sa = asb + s * TILE_HB;
        const uint32_t sb = bsb + s * TILE_HB;
#pragma unroll
        for (int j = 0; j < 4; j++) {
            cpasync16(sa + soff[j], aP + kk + j * 8);
            cpasync16(sb + soff[j], bP + kk + j * 8);
        }
        cp_commit();
    }

    for (int t = 0; t < ntiles; t++) {
        cp_wait<STAGES - 2>();
        __syncthreads();

        if (t + STAGES - 1 < ntiles) {
            const int s = (t + STAGES - 1) & (STAGES - 1);
            const int kk = (t + STAGES - 1) << 5;
            const uint32_t sa = asb + s * TILE_HB;
            const uint32_t sb = bsb + s * TILE_HB;
#pragma unroll
            for (int j = 0; j < 4; j++) {
                cpasync16(sa + soff[j], aP + kk + j * 8);
                cpasync16(sb + soff[j], bP + kk + j * 8);
            }
            cp_commit();
        }

        const int cur = t & (STAGES - 1);
        const uint32_t abuf = asb + cur * TILE_HB;
        const uint32_t bbuf = bsb + cur * TILE_HB;

#pragma unroll
        for (int s = 0; s < 2; s++) {
            uint32_t afr[4][4];
#pragma unroll
            for (int i = 0; i < 4; i++) {
                int m = wr * 64 + i * 16 + lm;
                int chunk = ((s << 1) + ach) ^ ((m >> 1) & 3);
                ldsm4(afr[i][0], afr[i][1], afr[i][2], afr[i][3],
                      abuf + (uint32_t)(m * 64 + chunk * 16));
            }
            uint32_t bfr[8][2];
#pragma unroll
            for (int jj = 0; jj < 4; jj++) {
                int ntile = wc * 8 + jj * 2 + bnt;
                int n = ntile * 8 + brow;
                int chunk = ((s << 1) + bch) ^ ((n >> 1) & 3);
                ldsm4(bfr[2 * jj][0], bfr[2 * jj][1], bfr[2 * jj + 1][0], bfr[2 * jj + 1][1],
                      bbuf + (uint32_t)(n * 64 + chunk * 16));
            }
#pragma unroll
            for (int i = 0; i < 4; i++)
#pragma unroll
                for (int j = 0; j < 8; j++)
                    mma_f16(acc[i][j], afr[i], bfr[j]);
        }
    }

    // epilogue
    const int r  = lane >> 2;
    const int cc = (lane & 3) << 1;
#pragma unroll
    for (int i = 0; i < 4; i++) {
        int row0 = bm + wr * 64 + i * 16 + r;
        int row1 = row0 + 8;
        int o0, o1;
        if (PERM == 0)      { o0 = row0;               o1 = row1; }
        else if (PERM == 1) { o0 = to_win_row(row0);   o1 = to_win_row(row1); }
        else                { o0 = from_win_row(row0); o1 = from_win_row(row1); }
#pragma unroll
        for (int j = 0; j < 8; j++) {
            int gn = bn + wc * 64 + j * 8 + cc;
            float b0 = bias[gn], b1 = bias[gn + 1];
            float v00 = acc[i][j][0] + b0, v01 = acc[i][j][1] + b1;
            float v10 = acc[i][j][2] + b0, v11 = acc[i][j][3] + b1;
            if (EPI == 1) {
                v00 = fmaxf(v00, 0.f); v01 = fmaxf(v01, 0.f);
                v10 = fmaxf(v10, 0.f); v11 = fmaxf(v11, 0.f);
            }
            if (OUTH) {
                __half* C = (__half*)Cv;
                *(__half2*)&C[(size_t)o0 * N + gn] = __floats2half2_rn(v00, v01);
                *(__half2*)&C[(size_t)o1 * N + gn] = __floats2half2_rn(v10, v11);
            } else {
                float* C = (float*)Cv;
                *(float2*)&C[(size_t)o0 * N + gn] = make_float2(v00, v01);
                *(float2*)&C[(size_t)o1 * N + gn] = make_float2(v10, v11);
            }
        }
    }
}

// ---------------------------------------------------------------------------
// Window attention: one block per (window, head). fp16 in/out, fp32 math.
// ---------------------------------------------------------------------------
__global__ void __launch_bounds__(256) attn_kernel(
    const __half* __restrict__ qkv, const float* __restrict__ pos_emb,
    __half* __restrict__ out)
{
    const int win = blockIdx.x;
    const int head = blockIdx.y;
    const int tid = threadIdx.x;

    __shared__ float Qt[32 * 68];
    __shared__ float Kt[32 * 68];
    __shared__ float Vs[64 * 36];
    __shared__ float Pt[64 * 68];
    __shared__ float bias_s[225];

    {
        int n  = tid >> 2;
        int c0 = (tid & 3) << 3;
        size_t base = ((size_t)win * 64 + n) * (size_t)QKV_N + head * HD_ + c0;
        {
            uint4 raw = *(const uint4*)(qkv + base);
            const __half2* h = (const __half2*)&raw;
#pragma unroll
            for (int j = 0; j < 4; j++) {
                float2 f = __half22float2(h[j]);
                Qt[(c0 + 2 * j) * 68 + n]     = f.x;
                Qt[(c0 + 2 * j + 1) * 68 + n] = f.y;
            }
        }
        {
            uint4 raw = *(const uint4*)(qkv + base + 512);
            const __half2* h = (const __half2*)&raw;
#pragma unroll
            for (int j = 0; j < 4; j++) {
                float2 f = __half22float2(h[j]);
                Kt[(c0 + 2 * j) * 68 + n]     = f.x;
                Kt[(c0 + 2 * j + 1) * 68 + n] = f.y;
            }
        }
        {
            uint4 raw = *(const uint4*)(qkv + base + 1024);
            const __half2* h = (const __half2*)&raw;
#pragma unroll
            for (int j = 0; j < 4; j++) {
                float2 f = __half22float2(h[j]);
                Vs[n * 36 + c0 + 2 * j]     = f.x;
                Vs[n * 36 + c0 + 2 * j + 1] = f.y;
            }
        }
    }
    if (tid < 225) bias_s[tid] = pos_emb[tid];
    __syncthreads();

    const int tq = tid >> 4;
    const int tk = tid & 15;

    float s[4][4];
#pragma unroll
    for (int a = 0; a < 4; a++)
#pragma unroll
        for (int b = 0; b < 4; b++) s[a][b] = 0.f;

#pragma unroll 8
    for (int d = 0; d < 32; d++) {
        float4 qf = *(const float4*)&Qt[d * 68 + tq * 4];
        float4 kf = *(const float4*)&Kt[d * 68 + tk * 4];
        const float* qa = (const float*)&qf;
        const float* ka = (const float*)&kf;
#pragma unroll
        for (int a = 0; a < 4; a++)
#pragma unroll
            for (int b = 0; b < 4; b++)
                s[a][b] = fmaf(qa[a], ka[b], s[a][b]);
    }

    const float scl = 0.17677669529663687f;
#pragma unroll
    for (int a = 0; a < 4; a++) {
        int q = tq * 4 + a, qh = q >> 3, qw = q & 7;
#pragma unroll
        for (int b = 0; b < 4; b++) {
            int k = tk * 4 + b, kh = k >> 3, kw = k & 7;
            s[a][b] = s[a][b] * scl + bias_s[(kh - qh + 7) * 15 + (kw - qw + 7)];
        }
    }

    float mx[4], sm[4];
#pragma unroll
    for (int a = 0; a < 4; a++)
        mx[a] = fmaxf(fmaxf(s[a][0], s[a][1]), fmaxf(s[a][2], s[a][3]));
#pragma unroll
    for (int off = 8; off; off >>= 1)
#pragma unroll
        for (int a = 0; a < 4; a++)
            mx[a] = fmaxf(mx[a], __shfl_xor_sync(0xffffffffu, mx[a], off));
#pragma unroll
    for (int a = 0; a < 4; a++) {
        sm[a] = 0.f;
#pragma unroll
        for (int b = 0; b < 4; b++) {
            s[a][b] = __expf(s[a][b] - mx[a]);
            sm[a] += s[a][b];
        }
    }
#pragma unroll
    for (int off = 8; off; off >>= 1)
#pragma unroll
        for (int a = 0; a < 4; a++)
            sm[a] += __shfl_xor_sync(0xffffffffu, sm[a], off);
    float inv[4];
#pragma unroll
    for (int a = 0; a < 4; a++) inv[a] = 1.f / sm[a];

#pragma unroll
    for (int b = 0; b < 4; b++) {
        float4 v = make_float4(s[0][b] * inv[0], s[1][b] * inv[1],
                               s[2][b] * inv[2], s[3][b] * inv[3]);
        *(float4*)&Pt[(tk * 4 + b) * 68 + tq * 4] = v;
    }
    __syncthreads();

    const int td = tid & 15;
    float o[4][2];
#pragma unroll
    for (int a = 0; a < 4; a++) { o[a][0] = 0.f; o[a][1] = 0.f; }
#pragma unroll 8
    for (int k = 0; k < 64; k++) {
        float4 pf = *(const float4*)&Pt[k * 68 + tq * 4];
        float2 vf = *(const float2*)&Vs[k * 36 + td * 2];
        const float* pa = (const float*)&pf;
#pragma unroll
        for (int a = 0; a < 4; a++) {
            o[a][0] = fmaf(pa[a], vf.x, o[a][0]);
            o[a][1] = fmaf(pa[a], vf.y, o[a][1]);
        }
    }
#pragma unroll
    for (int a = 0; a < 4; a++) {
        int q = tq * 4 + a;
        size_t ob = ((size_t)win * 64 + q) * (size_t)E_DIM + head * HD_ + td * 2;
        *(__half2*)&out[ob] = __floats2half2_rn(o[a][0], o[a][1]);
    }
}

// ---------------------------------------------------------------------------
// out = LayerNorm(a + b) * g + be ; optionally also fp16 copy.
// ---------------------------------------------------------------------------
template <int WH>
__global__ void __launch_bounds__(128) add_ln_kernel(
    const float* __restrict__ A, const float* __restrict__ Bv,
    const float* __restrict__ g, const float* __restrict__ be,
    float* __restrict__ out, __half* __restrict__ outh)
{
    const int row = blockIdx.x;
    const int tid = threadIdx.x;
    size_t base = (size_t)row * E_DIM + tid * 4;

    float4 a = *(const float4*)(A + base);
    float4 b = *(const float4*)(Bv + base);
    float y0 = a.x + b.x, y1 = a.y + b.y, y2 = a.z + b.z, y3 = a.w + b.w;

    float s  = y0 + y1 + y2 + y3;
    float s2 = y0 * y0 + y1 * y1 + y2 * y2 + y3 * y3;
#pragma unroll
    for (int off = 16; off; off >>= 1) {
        s  += __shfl_down_sync(0xffffffffu, s, off);
        s2 += __shfl_down_sync(0xffffffffu, s2, off);
    }
    __shared__ float ss[4], ss2[4];
    int warp = tid >> 5, lane = tid & 31;
    if (lane == 0) { ss[warp] = s; ss2[warp] = s2; }
    __syncthreads();
    s  = ss[0] + ss[1] + ss[2] + ss[3];
    s2 = ss2[0] + ss2[1] + ss2[2] + ss2[3];

    const float rE = 1.f / 512.f;
    float mean = s * rE;
    float var  = s2 * rE - mean * mean;
    float rstd = rsqrtf(var + 1e-5f);

    int e = tid * 4;
    float4 gw = *(const float4*)(g + e);
    float4 bb = *(const float4*)(be + e);
    float4 o;
    o.x = (y0 - mean) * rstd * gw.x + bb.x;
    o.y = (y1 - mean) * rstd * gw.y + bb.y;
    o.z = (y2 - mean) * rstd * gw.z + bb.z;
    o.w = (y3 - mean) * rstd * gw.w + bb.w;
    *(float4*)(out + base) = o;
    if (WH) {
        *(__half2*)(outh + base)     = __floats2half2_rn(o.x, o.y);
        *(__half2*)(outh + base + 2) = __floats2half2_rn(o.z, o.w);
    }
}

// ---------------------------------------------------------------------------
extern "C" void kernel_launch(void* const* d_in, const int* in_sizes, int n_in,
                              void* d_out, int out_size)
{
    const float* x     = (const float*)d_in[0];
    const float* w_qkv = (const float*)d_in[1];
    const float* b_qkv = (const float*)d_in[2];
    const float* w_out = (const float*)d_in[3];
    const float* b_out = (const float*)d_in[4];
    const float* pos   = (const float*)d_in[5];
    const float* w1    = (const float*)d_in[6];
    const float* b1    = (const float*)d_in[7];
    const float* w2    = (const float*)d_in[8];
    const float* b2    = (const float*)d_in[9];
    const float* ln1w  = (const float*)d_in[10];
    const float* ln1b  = (const float*)d_in[11];
    const float* ln2w  = (const float*)d_in[12];
    const float* ln2b  = (const float*)d_in[13];
    float* out = (float*)d_out;

    static float *p_t0 = nullptr, *p_z = nullptr;
    static __half *p_x16 = nullptr, *p_z16 = nullptr, *p_qkv16 = nullptr,
                  *p_attn16 = nullptr, *p_h16 = nullptr,
                  *p_wqkv16 = nullptr, *p_wout16 = nullptr,
                  *p_w116 = nullptr, *p_w216 = nullptr;
    static bool inited = false;
    if (!inited) {
        cudaGetSymbolAddress((void**)&p_t0,     g_t0);
        cudaGetSymbolAddress((void**)&p_z,      g_z);
        cudaGetSymbolAddress((void**)&p_x16,    g_x16);
        cudaGetSymbolAddress((void**)&p_z16,    g_z16);
        cudaGetSymbolAddress((void**)&p_qkv16,  g_qkv16);
        cudaGetSymbolAddress((void**)&p_attn16, g_attn16);
        cudaGetSymbolAddress((void**)&p_h16,    g_h16);
        cudaGetSymbolAddress((void**)&p_wqkv16, g_wqkv16);
        cudaGetSymbolAddress((void**)&p_wout16, g_wout16);
        cudaGetSymbolAddress((void**)&p_w116,   g_w116);
        cudaGetSymbolAddress((void**)&p_w216,   g_w216);
        cudaFuncSetAttribute(gemm_f16<0, 1, 1>, cudaFuncAttributeMaxDynamicSharedMemorySize, GSM_BYTES);
        cudaFuncSetAttribute(gemm_f16<0, 2, 0>, cudaFuncAttributeMaxDynamicSharedMemorySize, GSM_BYTES);
        cudaFuncSetAttribute(gemm_f16<1, 0, 1>, cudaFuncAttributeMaxDynamicSharedMemorySize, GSM_BYTES);
        cudaFuncSetAttribute(gemm_f16<0, 0, 0>, cudaFuncAttributeMaxDynamicSharedMemorySize, GSM_BYTES);
        inited = true;
    }

    // 0. fp32 -> fp16 conversions (x + weights)
    {
        int n;
        n = T_TOK * E_DIM;
        cvt_f16_kernel<<<n / (256 * 4), 256>>>(x, p_x16, n);
        n = QKV_N * E_DIM;
        cvt_f16_kernel<<<n / (256 * 4), 256>>>(w_qkv, p_wqkv16, n);
        n = E_DIM * E_DIM;
        cvt_f16_kernel<<<n / (256 * 4), 256>>>(w_out, p_wout16, n);
        n = DFF_N * E_DIM;
        cvt_f16_kernel<<<n / (256 * 4), 256>>>(w1, p_w116, n);
        n = E_DIM * DFF_N;
        cvt_f16_kernel<<<n / (256 * 4), 256>>>(w2, p_w216, n);
    }

    // 1. QKV projection -> window layout (fp16 out)
    gemm_f16<0, 1, 1><<<dim3(QKV_N / 128, T_TOK / 128), 128, GSM_BYTES>>>(
        p_x16, p_wqkv16, b_qkv, p_qkv16, T_TOK, QKV_N, E_DIM);

    // 2. window attention (fp16 in/out)
    attn_kernel<<<dim3(NWIN, NH_), 256>>>(p_qkv16, pos, p_attn16);

    // 3. output projection -> token layout (fp32 out)
    gemm_f16<0, 2, 0><<<dim3(E_DIM / 128, T_TOK / 128), 128, GSM_BYTES>>>(
        p_attn16, p_wout16, b_out, p_t0, T_TOK, E_DIM, E_DIM);

    // 4. residual + LN1 -> z (fp32) + z16
    add_ln_kernel<1><<<T_TOK, 128>>>(x, p_t0, ln1w, ln1b, p_z, p_z16);

    // 5. FFN up + ReLU (fp16 out)
    gemm_f16<1, 0, 1><<<dim3(DFF_N / 128, T_TOK / 128), 128, GSM_BYTES>>>(
        p_z16, p_w116, b1, p_h16, T_TOK, DFF_N, E_DIM);

    // 6. FFN down (fp32 out)
    gemm_f16<0, 0, 0><<<dim3(E_DIM / 128, T_TOK / 128), 128, GSM_BYTES>>>(
        p_h16, p_w216, b2, p_t0, T_TOK, E_DIM, DFF_N);

    // 7. residual + LN2 -> output
    add_ln_kernel<0><<<T_TOK, 128>>>(p_z, p_t0, ln2w, ln2b, out, nullptr);
}

// round 15
// speedup vs baseline: 1.2040x; 1.2040x over previous
#include <cuda_runtime.h>
#include <cuda_fp16.h>
#include <cstdint>
#include <math.h>

// ---------------------------------------------------------------------------
// Swin Transformer encoder layer, GB300 round-15:
// R13 fp16 GEMM pipeline (BK=16, 4 stages, 2x2 warps, 64x64 tiles) with
// 3 CTAs/SM (170 regs/thread cap -- fits the ~160 live values).
// ---------------------------------------------------------------------------

#define T_TOK   65536
#define E_DIM   512
#define QKV_N   1536
#define DFF_N   2048
#define NWIN    1024
#define NH_     16
#define HD_     32

// fp32 scratch
__device__ float g_t0[(size_t)T_TOK * E_DIM];
__device__ float g_z[(size_t)T_TOK * E_DIM];
// fp16 scratch
__device__ __half g_x16[(size_t)T_TOK * E_DIM];
__device__ __half g_z16[(size_t)T_TOK * E_DIM];
__device__ __half g_qkv16[(size_t)T_TOK * QKV_N];
__device__ __half g_attn16[(size_t)T_TOK * E_DIM];
__device__ __half g_h16[(size_t)T_TOK * DFF_N];
__device__ __half g_wqkv16[(size_t)QKV_N * E_DIM];
__device__ __half g_wout16[(size_t)E_DIM * E_DIM];
__device__ __half g_w116[(size_t)DFF_N * E_DIM];
__device__ __half g_w216[(size_t)E_DIM * DFF_N];

__device__ __forceinline__ int to_win_row(int m) {
    int b = m >> 14, p = m & 16383;
    int r = p >> 7, c = p & 127;
    int win = (b << 8) + ((r >> 3) << 4) + (c >> 3);
    int n   = ((r & 7) << 3) + (c & 7);
    return (win << 6) + n;
}
__device__ __forceinline__ int from_win_row(int m) {
    int win = m >> 6, n = m & 63;
    int b  = win >> 8, wi = win & 255;
    int wr = wi >> 4,  wc = wi & 15;
    int r = (wr << 3) + (n >> 3);
    int c = (wc << 3) + (n & 7);
    return (b << 14) + (r << 7) + c;
}

__device__ __forceinline__ void mma_f16(float c[4], const uint32_t a[4], const uint32_t b[2]) {
    asm volatile(
        "mma.sync.aligned.m16n8k16.row.col.f32.f16.f16.f32 "
        "{%0,%1,%2,%3},{%4,%5,%6,%7},{%8,%9},{%0,%1,%2,%3};\n"
        : "+f"(c[0]), "+f"(c[1]), "+f"(c[2]), "+f"(c[3])
        : "r"(a[0]), "r"(a[1]), "r"(a[2]), "r"(a[3]), "r"(b[0]), "r"(b[1]));
}

__device__ __forceinline__ void ldsm4(uint32_t& r0, uint32_t& r1, uint32_t& r2, uint32_t& r3,
                                      uint32_t addr) {
    asm volatile("ldmatrix.sync.aligned.m8n8.x4.shared.b16 {%0,%1,%2,%3}, [%4];"
                 : "=r"(r0), "=r"(r1), "=r"(r2), "=r"(r3) : "r"(addr));
}

__device__ __forceinline__ void cpasync16(uint32_t dst, const void* src) {
    asm volatile("cp.async.cg.shared.global [%0], [%1], 16;" :: "r"(dst), "l"(src));
}
__device__ __forceinline__ void cp_commit() {
    asm volatile("cp.async.commit_group;" ::: "memory");
}
template <int N>
__device__ __forceinline__ void cp_wait() {
    asm volatile("cp.async.wait_group %0;" :: "n"(N) : "memory");
}

// ---------------------------------------------------------------------------
// fp32 -> fp16 conversion (4 elems/thread)
// ---------------------------------------------------------------------------
__global__ void cvt_f16_kernel(const float* __restrict__ src, __half* __restrict__ dst, int n) {
    int i = (blockIdx.x * blockDim.x + threadIdx.x) * 4;
    if (i < n) {
        float4 v = *(const float4*)(src + i);
        *(__half2*)(dst + i)     = __floats2half2_rn(v.x, v.y);
        *(__half2*)(dst + i + 2) = __floats2half2_rn(v.z, v.w);
    }
}

// ---------------------------------------------------------------------------
// fp16 NT GEMM: C[m][n] = sum_k A[m][k]*B[n][k] + bias[n]  (fp32 accumulate)
// Block 128x128, BK=16, 128 threads = 4 warps (2m x 2n), warp tile 64x64.
// Smem: k-major 128x16 fp16 tiles (32B rows), swizzle chunk ^= (row>>2)&1;
// 4-stage cp.async ring; ldmatrix.x4.b16 fragment reads. 3 CTAs/SM.
// EPI: 0 bias, 1 bias+relu.  PERM: 0 none, 1 to_win, 2 from_win.
// OUTH: 1 -> __half C, 0 -> float C.
// ---------------------------------------------------------------------------
#define STAGES 4
#define TILE_HB 4096                      // 128 rows * 32 bytes
#define GSM_BYTES (STAGES * TILE_HB * 2)  // 32 KB

template <int EPI, int PERM, int OUTH>
__global__ void __launch_bounds__(128, 3) gemm_f16(
    const __half* __restrict__ A, const __half* __restrict__ B,
    const float* __restrict__ bias, void* __restrict__ Cv,
    int M, int N, int K)
{
    extern __shared__ __align__(128) uint32_t smem[];
    const uint32_t asb = (uint32_t)__cvta_generic_to_shared(smem);
    const uint32_t bsb = asb + STAGES * TILE_HB;

    const int tid  = threadIdx.x;
    const int lane = tid & 31;
    const int warp = tid >> 5;
    const int wr = warp >> 1;        // m half (64 rows)
    const int wc = warp & 1;         // n half (64 cols)
    const int bm = blockIdx.y << 7;
    const int bn = blockIdx.x << 7;

    // loader: thread -> rows tid>>1 and +64, chunk = tid&1 (16B = 8 fp16)
    const int lrow = tid >> 1;             // 0..63
    const int lch  = tid & 1;
    const int swc  = lch ^ ((lrow >> 2) & 1);
    const uint32_t off0 = (uint32_t)(lrow * 32 + swc * 16);   // byte offset

    const __half* aP0 = A + (size_t)(bm + lrow) * K + lch * 8;
    const __half* aP1 = A + (size_t)(bm + lrow + 64) * K + lch * 8;
    const __half* bP0 = B + (size_t)(bn + lrow) * K + lch * 8;
    const __half* bP1 = B + (size_t)(bn + lrow + 64) * K + lch * 8;

    // ldmatrix lane invariants
    const int lm    = (lane & 7) + (((lane >> 3) & 1) << 3);   // A row in 16
    const int ach   = lane >> 4;                                // A k-chunk
    const int aswp  = (lm >> 2) & 1;
    const int brow  = lane & 7;                                 // B row in 8
    const int bch   = (lane >> 3) & 1;                          // B k-chunk
    const int bnt   = (lane >> 4) & 1;                          // B ntile sel
    const int bswp  = (brow >> 2) & 1;

    float acc[4][8][4];
#pragma unroll
    for (int i = 0; i < 4; i++)
#pragma unroll
        for (int j = 0; j < 8; j++)
#pragma unroll
            for (int v = 0; v < 4; v++) acc[i][j][v] = 0.f;

    const int ntiles = K >> 4;

    // prologue: stages 0..2
#pragma unroll
    for (int s = 0; s < STAGES - 1; s++) {
        const int kk = s << 4;
        const uint32_t sa = asb + s * TILE_HB;
        const uint32_t sb = bsb + s * TILE_HB;
        cpasync16(sa + off0,        aP0 + kk);
        cpasync16(sa + off0 + 2048, aP1 + kk);
        cpasync16(sb + off0,        bP0 + kk);
        cpasync16(sb + off0 + 2048, bP1 + kk);
        cp_commit();
    }

    for (int t = 0; t < ntiles; t++) {
        cp_wait<STAGES - 2>();
        __syncthreads();

        if (t + STAGES - 1 < ntiles) {
            const int s = (t + STAGES - 1) & (STAGES - 1);
            const int kk = (t + STAGES - 1) << 4;
            const uint32_t sa = asb + s * TILE_HB;
            const uint32_t sb = bsb + s * TILE_HB;
            cpasync16(sa + off0,        aP0 + kk);
            cpasync16(sa + off0 + 2048, aP1 + kk);
            cpasync16(sb + off0,        bP0 + kk);
            cpasync16(sb + off0 + 2048, bP1 + kk);
            cp_commit();
        }

        const int cur = t & (STAGES - 1);
        const uint32_t abuf = asb + cur * TILE_HB;
        const uint32_t bbuf = bsb + cur * TILE_HB;

        uint32_t afr[4][4];
#pragma unroll
        for (int i = 0; i < 4; i++) {
            int row = wr * 64 + i * 16 + lm;
            int chunk = ach ^ aswp;
            ldsm4(afr[i][0], afr[i][1], afr[i][2], afr[i][3],
                  abuf + (uint32_t)(row * 32 + chunk * 16));
        }
        uint32_t bfr[8][2];
#pragma unroll
        for (int jj = 0; jj < 4; jj++) {
            int ntile = wc * 8 + jj * 2 + bnt;
            int n = ntile * 8 + brow;
            int chunk = bch ^ bswp;
            ldsm4(bfr[2 * jj][0], bfr[2 * jj][1], bfr[2 * jj + 1][0], bfr[2 * jj + 1][1],
                  bbuf + (uint32_t)(n * 32 + chunk * 16));
        }
#pragma unroll
        for (int i = 0; i < 4; i++)
#pragma unroll
            for (int j = 0; j < 8; j++)
                mma_f16(acc[i][j], afr[i], bfr[j]);
    }

    // epilogue
    const int r  = lane >> 2;
    const int cc = (lane & 3) << 1;
#pragma unroll
    for (int i = 0; i < 4; i++) {
        int row0 = bm + wr * 64 + i * 16 + r;
        int row1 = row0 + 8;
        int o0, o1;
        if (PERM == 0)      { o0 = row0;               o1 = row1; }
        else if (PERM == 1) { o0 = to_win_row(row0);   o1 = to_win_row(row1); }
        else                { o0 = from_win_row(row0); o1 = from_win_row(row1); }
#pragma unroll
        for (int j = 0; j < 8; j++) {
            int gn = bn + wc * 64 + j * 8 + cc;
            float b0 = bias[gn], b1 = bias[gn + 1];
            float v00 = acc[i][j][0] + b0, v01 = acc[i][j][1] + b1;
            float v10 = acc[i][j][2] + b0, v11 = acc[i][j][3] + b1;
            if (EPI == 1) {
                v00 = fmaxf(v00, 0.f); v01 = fmaxf(v01, 0.f);
                v10 = fmaxf(v10, 0.f); v11 = fmaxf(v11, 0.f);
            }
            if (OUTH) {
                __half* C = (__half*)Cv;
                *(__half2*)&C[(size_t)o0 * N + gn] = __floats2half2_rn(v00, v01);
                *(__half2*)&C[(size_t)o1 * N + gn] = __floats2half2_rn(v10, v11);
            } else {
                float* C = (float*)Cv;
                *(float2*)&C[(size_t)o0 * N + gn] = make_float2(v00, v01);
                *(float2*)&C[(size_t)o1 * N + gn] = make_float2(v10, v11);
            }
        }
    }
}

// ---------------------------------------------------------------------------
// Window attention: one block per (window, head). fp16 in/out, fp32 math.
// ---------------------------------------------------------------------------
__global__ void __launch_bounds__(256) attn_kernel(
    const __half* __restrict__ qkv, const float* __restrict__ pos_emb,
    __half* __restrict__ out)
{
    const int win = blockIdx.x;
    const int head = blockIdx.y;
    const int tid = threadIdx.x;

    __shared__ float Qt[32 * 68];
    __shared__ float Kt[32 * 68];
    __shared__ float Vs[64 * 36];
    __shared__ float Pt[64 * 68];
    __shared__ float bias_s[225];

    {
        int n  = tid >> 2;
        int c0 = (tid & 3) << 3;
        size_t base = ((size_t)win * 64 + n) * (size_t)QKV_N + head * HD_ + c0;
        {
            uint4 raw = *(const uint4*)(qkv + base);
            const __half2* h = (const __half2*)&raw;
#pragma unroll
            for (int j = 0; j < 4; j++) {
                float2 f = __half22float2(h[j]);
                Qt[(c0 + 2 * j) * 68 + n]     = f.x;
                Qt[(c0 + 2 * j + 1) * 68 + n] = f.y;
            }
        }
        {
            uint4 raw = *(const uint4*)(qkv + base + 512);
            const __half2* h = (const __half2*)&raw;
#pragma unroll
            for (int j = 0; j < 4; j++) {
                float2 f = __half22float2(h[j]);
                Kt[(c0 + 2 * j) * 68 + n]     = f.x;
                Kt[(c0 + 2 * j + 1) * 68 + n] = f.y;
            }
        }
        {
            uint4 raw = *(const uint4*)(qkv + base + 1024);
            const __half2* h = (const __half2*)&raw;
#pragma unroll
            for (int j = 0; j < 4; j++) {
                float2 f = __half22float2(h[j]);
                Vs[n * 36 + c0 + 2 * j]     = f.x;
                Vs[n * 36 + c0 + 2 * j + 1] = f.y;
            }
        }
    }
    if (tid < 225) bias_s[tid] = pos_emb[tid];
    __syncthreads();

    const int tq = tid >> 4;
    const int tk = tid & 15;

    float s[4][4];
#pragma unroll
    for (int a = 0; a < 4; a++)
#pragma unroll
        for (int b = 0; b < 4; b++) s[a][b] = 0.f;

#pragma unroll 8
    for (int d = 0; d < 32; d++) {
        float4 qf = *(const float4*)&Qt[d * 68 + tq * 4];
        float4 kf = *(const float4*)&Kt[d * 68 + tk * 4];
        const float* qa = (const float*)&qf;
        const float* ka = (const float*)&kf;
#pragma unroll
        for (int a = 0; a < 4; a++)
#pragma unroll
            for (int b = 0; b < 4; b++)
                s[a][b] = fmaf(qa[a], ka[b], s[a][b]);
    }

    const float scl = 0.17677669529663687f;
#pragma unroll
    for (int a = 0; a < 4; a++) {
        int q = tq * 4 + a, qh = q >> 3, qw = q & 7;
#pragma unroll
        for (int b = 0; b < 4; b++) {
            int k = tk * 4 + b, kh = k >> 3, kw = k & 7;
            s[a][b] = s[a][b] * scl + bias_s[(kh - qh + 7) * 15 + (kw - qw + 7)];
        }
    }

    float mx[4], sm[4];
#pragma unroll
    for (int a = 0; a < 4; a++)
        mx[a] = fmaxf(fmaxf(s[a][0], s[a][1]), fmaxf(s[a][2], s[a][3]));
#pragma unroll
    for (int off = 8; off; off >>= 1)
#pragma unroll
        for (int a = 0; a < 4; a++)
            mx[a] = fmaxf(mx[a], __shfl_xor_sync(0xffffffffu, mx[a], off));
#pragma unroll
    for (int a = 0; a < 4; a++) {
        sm[a] = 0.f;
#pragma unroll
        for (int b = 0; b < 4; b++) {
            s[a][b] = __expf(s[a][b] - mx[a]);
            sm[a] += s[a][b];
        }
    }
#pragma unroll
    for (int off = 8; off; off >>= 1)
#pragma unroll
        for (int a = 0; a < 4; a++)
            sm[a] += __shfl_xor_sync(0xffffffffu, sm[a], off);
    float inv[4];
#pragma unroll
    for (int a = 0; a < 4; a++) inv[a] = 1.f / sm[a];

#pragma unroll
    for (int b = 0; b < 4; b++) {
        float4 v = make_float4(s[0][b] * inv[0], s[1][b] * inv[1],
                               s[2][b] * inv[2], s[3][b] * inv[3]);
        *(float4*)&Pt[(tk * 4 + b) * 68 + tq * 4] = v;
    }
    __syncthreads();

    const int td = tid & 15;
    float o[4][2];
#pragma unroll
    for (int a = 0; a < 4; a++) { o[a][0] = 0.f; o[a][1] = 0.f; }
#pragma unroll 8
    for (int k = 0; k < 64; k++) {
        float4 pf = *(const float4*)&Pt[k * 68 + tq * 4];
        float2 vf = *(const float2*)&Vs[k * 36 + td * 2];
        const float* pa = (const float*)&pf;
#pragma unroll
        for (int a = 0; a < 4; a++) {
            o[a][0] = fmaf(pa[a], vf.x, o[a][0]);
            o[a][1] = fmaf(pa[a], vf.y, o[a][1]);
        }
    }
#pragma unroll
    for (int a = 0; a < 4; a++) {
        int q = tq * 4 + a;
        size_t ob = ((size_t)win * 64 + q) * (size_t)E_DIM + head * HD_ + td * 2;
        *(__half2*)&out[ob] = __floats2half2_rn(o[a][0], o[a][1]);
    }
}

// ---------------------------------------------------------------------------
// out = LayerNorm(a + b) * g + be ; optionally also fp16 copy.
// ---------------------------------------------------------------------------
template <int WH>
__global__ void __launch_bounds__(128) add_ln_kernel(
    const float* __restrict__ A, const float* __restrict__ Bv,
    const float* __restrict__ g, const float* __restrict__ be,
    float* __restrict__ out, __half* __restrict__ outh)
{
    const int row = blockIdx.x;
    const int tid = threadIdx.x;
    size_t base = (size_t)row * E_DIM + tid * 4;

    float4 a = *(const float4*)(A + base);
    float4 b = *(const float4*)(Bv + base);
    float y0 = a.x + b.x, y1 = a.y + b.y, y2 = a.z + b.z, y3 = a.w + b.w;

    float s  = y0 + y1 + y2 + y3;
    float s2 = y0 * y0 + y1 * y1 + y2 * y2 + y3 * y3;
#pragma unroll
    for (int off = 16; off; off >>= 1) {
        s  += __shfl_down_sync(0xffffffffu, s, off);
        s2 += __shfl_down_sync(0xffffffffu, s2, off);
    }
    __shared__ float ss[4], ss2[4];
    int warp = tid >> 5, lane = tid & 31;
    if (lane == 0) { ss[warp] = s; ss2[warp] = s2; }
    __syncthreads();
    s  = ss[0] + ss[1] + ss[2] + ss[3];
    s2 = ss2[0] + ss2[1] + ss2[2] + ss2[3];

    const float rE = 1.f / 512.f;
    float mean = s * rE;
    float var  = s2 * rE - mean * mean;
    float rstd = rsqrtf(var + 1e-5f);

    int e = tid * 4;
    float4 gw = *(const float4*)(g + e);
    float4 bb = *(const float4*)(be + e);
    float4 o;
    o.x = (y0 - mean) * rstd * gw.x + bb.x;
    o.y = (y1 - mean) * rstd * gw.y + bb.y;
    o.z = (y2 - mean) * rstd * gw.z + bb.z;
    o.w = (y3 - mean) * rstd * gw.w + bb.w;
    *(float4*)(out + base) = o;
    if (WH) {
        *(__half2*)(outh + base)     = __floats2half2_rn(o.x, o.y);
        *(__half2*)(outh + base + 2) = __floats2half2_rn(o.z, o.w);
    }
}

// ---------------------------------------------------------------------------
extern "C" void kernel_launch(void* const* d_in, const int* in_sizes, int n_in,
                              void* d_out, int out_size)
{
    const float* x     = (const float*)d_in[0];
    const float* w_qkv = (const float*)d_in[1];
    const float* b_qkv = (const float*)d_in[2];
    const float* w_out = (const float*)d_in[3];
    const float* b_out = (const float*)d_in[4];
    const float* pos   = (const float*)d_in[5];
    const float* w1    = (const float*)d_in[6];
    const float* b1    = (const float*)d_in[7];
    const float* w2    = (const float*)d_in[8];
    const float* b2    = (const float*)d_in[9];
    const float* ln1w  = (const float*)d_in[10];
    const float* ln1b  = (const float*)d_in[11];
    const float* ln2w  = (const float*)d_in[12];
    const float* ln2b  = (const float*)d_in[13];
    float* out = (float*)d_out;

    static float *p_t0 = nullptr, *p_z = nullptr;
    static __half *p_x16 = nullptr, *p_z16 = nullptr, *p_qkv16 = nullptr,
                  *p_attn16 = nullptr, *p_h16 = nullptr,
                  *p_wqkv16 = nullptr, *p_wout16 = nullptr,
                  *p_w116 = nullptr, *p_w216 = nullptr;
    static bool inited = false;
    if (!inited) {
        cudaGetSymbolAddress((void**)&p_t0,     g_t0);
        cudaGetSymbolAddress((void**)&p_z,      g_z);
        cudaGetSymbolAddress((void**)&p_x16,    g_x16);
        cudaGetSymbolAddress((void**)&p_z16,    g_z16);
        cudaGetSymbolAddress((void**)&p_qkv16,  g_qkv16);
        cudaGetSymbolAddress((void**)&p_attn16, g_attn16);
        cudaGetSymbolAddress((void**)&p_h16,    g_h16);
        cudaGetSymbolAddress((void**)&p_wqkv16, g_wqkv16);
        cudaGetSymbolAddress((void**)&p_wout16, g_wout16);
        cudaGetSymbolAddress((void**)&p_w116,   g_w116);
        cudaGetSymbolAddress((void**)&p_w216,   g_w216);
        cudaFuncSetAttribute(gemm_f16<0, 1, 1>, cudaFuncAttributeMaxDynamicSharedMemorySize, GSM_BYTES);
        cudaFuncSetAttribute(gemm_f16<0, 2, 0>, cudaFuncAttributeMaxDynamicSharedMemorySize, GSM_BYTES);
        cudaFuncSetAttribute(gemm_f16<1, 0, 1>, cudaFuncAttributeMaxDynamicSharedMemorySize, GSM_BYTES);
        cudaFuncSetAttribute(gemm_f16<0, 0, 0>, cudaFuncAttributeMaxDynamicSharedMemorySize, GSM_BYTES);
        inited = true;
    }

    // 0. fp32 -> fp16 conversions (x + weights)
    {
        int n;
        n = T_TOK * E_DIM;
        cvt_f16_kernel<<<n / (256 * 4), 256>>>(x, p_x16, n);
        n = QKV_N * E_DIM;
        cvt_f16_kernel<<<n / (256 * 4), 256>>>(w_qkv, p_wqkv16, n);
        n = E_DIM * E_DIM;
        cvt_f16_kernel<<<n / (256 * 4), 256>>>(w_out, p_wout16, n);
        n = DFF_N * E_DIM;
        cvt_f16_kernel<<<n / (256 * 4), 256>>>(w1, p_w116, n);
        n = E_DIM * DFF_N;
        cvt_f16_kernel<<<n / (256 * 4), 256>>>(w2, p_w216, n);
    }

    // 1. QKV projection -> window layout (fp16 out)
    gemm_f16<0, 1, 1><<<dim3(QKV_N / 128, T_TOK / 128), 128, GSM_BYTES>>>(
        p_x16, p_wqkv16, b_qkv, p_qkv16, T_TOK, QKV_N, E_DIM);

    // 2. window attention (fp16 in/out)
    attn_kernel<<<dim3(NWIN, NH_), 256>>>(p_qkv16, pos, p_attn16);

    // 3. output projection -> token layout (fp32 out)
    gemm_f16<0, 2, 0><<<dim3(E_DIM / 128, T_TOK / 128), 128, GSM_BYTES>>>(
        p_attn16, p_wout16, b_out, p_t0, T_TOK, E_DIM, E_DIM);

    // 4. residual + LN1 -> z (fp32) + z16
    add_ln_kernel<1><<<T_TOK, 128>>>(x, p_t0, ln1w, ln1b, p_z, p_z16);

    // 5. FFN up + ReLU (fp16 out)
    gemm_f16<1, 0, 1><<<dim3(DFF_N / 128, T_TOK / 128), 128, GSM_BYTES>>>(
        p_z16, p_w116, b1, p_h16, T_TOK, DFF_N, E_DIM);

    // 6. FFN down (fp32 out)
    gemm_f16<0, 0, 0><<<dim3(E_DIM / 128, T_TOK / 128), 128, GSM_BYTES>>>(
        p_h16, p_w216, b2, p_t0, T_TOK, E_DIM, DFF_N);

    // 7. residual + LN2 -> output
    add_ln_kernel<0><<<T_TOK, 128>>>(p_z, p_t0, ln2w, ln2b, out, nullptr);
}

// round 16
// speedup vs baseline: 1.4705x; 1.2214x over previous
#include <cuda_runtime.h>
#include <cuda_fp16.h>
#include <cstdint>
#include <math.h>

// ---------------------------------------------------------------------------
// Swin Transformer encoder layer, GB300 round-16:
// R13 fp16 GEMMs (converged shape) + fp16 intermediate tail:
// out-proj/FFN2 write fp16; LN1 emits fp16-only z; LN2 reads fp16 residual.
// ---------------------------------------------------------------------------

#define T_TOK   65536
#define E_DIM   512
#define QKV_N   1536
#define DFF_N   2048
#define NWIN    1024
#define NH_     16
#define HD_     32

// fp16 scratch
__device__ __half g_x16[(size_t)T_TOK * E_DIM];
__device__ __half g_z16[(size_t)T_TOK * E_DIM];
__device__ __half g_t0h[(size_t)T_TOK * E_DIM];
__device__ __half g_t2h[(size_t)T_TOK * E_DIM];
__device__ __half g_qkv16[(size_t)T_TOK * QKV_N];
__device__ __half g_attn16[(size_t)T_TOK * E_DIM];
__device__ __half g_h16[(size_t)T_TOK * DFF_N];
__device__ __half g_wqkv16[(size_t)QKV_N * E_DIM];
__device__ __half g_wout16[(size_t)E_DIM * E_DIM];
__device__ __half g_w116[(size_t)DFF_N * E_DIM];
__device__ __half g_w216[(size_t)E_DIM * DFF_N];

__device__ __forceinline__ int to_win_row(int m) {
    int b = m >> 14, p = m & 16383;
    int r = p >> 7, c = p & 127;
    int win = (b << 8) + ((r >> 3) << 4) + (c >> 3);
    int n   = ((r & 7) << 3) + (c & 7);
    return (win << 6) + n;
}
__device__ __forceinline__ int from_win_row(int m) {
    int win = m >> 6, n = m & 63;
    int b  = win >> 8, wi = win & 255;
    int wr = wi >> 4,  wc = wi & 15;
    int r = (wr << 3) + (n >> 3);
    int c = (wc << 3) + (n & 7);
    return (b << 14) + (r << 7) + c;
}

__device__ __forceinline__ void mma_f16(float c[4], const uint32_t a[4], const uint32_t b[2]) {
    asm volatile(
        "mma.sync.aligned.m16n8k16.row.col.f32.f16.f16.f32 "
        "{%0,%1,%2,%3},{%4,%5,%6,%7},{%8,%9},{%0,%1,%2,%3};\n"
        : "+f"(c[0]), "+f"(c[1]), "+f"(c[2]), "+f"(c[3])
        : "r"(a[0]), "r"(a[1]), "r"(a[2]), "r"(a[3]), "r"(b[0]), "r"(b[1]));
}

__device__ __forceinline__ void ldsm4(uint32_t& r0, uint32_t& r1, uint32_t& r2, uint32_t& r3,
                                      uint32_t addr) {
    asm volatile("ldmatrix.sync.aligned.m8n8.x4.shared.b16 {%0,%1,%2,%3}, [%4];"
                 : "=r"(r0), "=r"(r1), "=r"(r2), "=r"(r3) : "r"(addr));
}

__device__ __forceinline__ void cpasync16(uint32_t dst, const void* src) {
    asm volatile("cp.async.cg.shared.global [%0], [%1], 16;" :: "r"(dst), "l"(src));
}
__device__ __forceinline__ void cp_commit() {
    asm volatile("cp.async.commit_group;" ::: "memory");
}
template <int N>
__device__ __forceinline__ void cp_wait() {
    asm volatile("cp.async.wait_group %0;" :: "n"(N) : "memory");
}

// ---------------------------------------------------------------------------
// fp32 -> fp16 conversion (4 elems/thread)
// ---------------------------------------------------------------------------
__global__ void cvt_f16_kernel(const float* __restrict__ src, __half* __restrict__ dst, int n) {
    int i = (blockIdx.x * blockDim.x + threadIdx.x) * 4;
    if (i < n) {
        float4 v = *(const float4*)(src + i);
        *(__half2*)(dst + i)     = __floats2half2_rn(v.x, v.y);
        *(__half2*)(dst + i + 2) = __floats2half2_rn(v.z, v.w);
    }
}

// ---------------------------------------------------------------------------
// fp16 NT GEMM: C[m][n] = sum_k A[m][k]*B[n][k] + bias[n]  (fp32 accumulate,
// fp16 output). R13 converged shape: block 128x128, BK=16, 128 threads =
// 4 warps (2m x 2n), warp tile 64x64; 32B smem rows, swizzle chunk^=(row>>2)&1;
// 4-stage cp.async ring; ldmatrix.x4.b16 reads; 2 CTAs/SM.
// EPI: 0 bias, 1 bias+relu.  PERM: 0 none, 1 to_win, 2 from_win.
// ---------------------------------------------------------------------------
#define STAGES 4
#define TILE_HB 4096
#define GSM_BYTES (STAGES * TILE_HB * 2)  // 32 KB

template <int EPI, int PERM>
__global__ void __launch_bounds__(128, 2) gemm_f16(
    const __half* __restrict__ A, const __half* __restrict__ B,
    const float* __restrict__ bias, __half* __restrict__ C,
    int M, int N, int K)
{
    extern __shared__ __align__(128) uint32_t smem[];
    const uint32_t asb = (uint32_t)__cvta_generic_to_shared(smem);
    const uint32_t bsb = asb + STAGES * TILE_HB;

    const int tid  = threadIdx.x;
    const int lane = tid & 31;
    const int warp = tid >> 5;
    const int wr = warp >> 1;
    const int wc = warp & 1;
    const int bm = blockIdx.y << 7;
    const int bn = blockIdx.x << 7;

    const int lrow = tid >> 1;
    const int lch  = tid & 1;
    const int swc  = lch ^ ((lrow >> 2) & 1);
    const uint32_t off0 = (uint32_t)(lrow * 32 + swc * 16);

    const __half* aP0 = A + (size_t)(bm + lrow) * K + lch * 8;
    const __half* aP1 = A + (size_t)(bm + lrow + 64) * K + lch * 8;
    const __half* bP0 = B + (size_t)(bn + lrow) * K + lch * 8;
    const __half* bP1 = B + (size_t)(bn + lrow + 64) * K + lch * 8;

    const int lm    = (lane & 7) + (((lane >> 3) & 1) << 3);
    const int ach   = lane >> 4;
    const int aswp  = (lm >> 2) & 1;
    const int brow  = lane & 7;
    const int bch   = (lane >> 3) & 1;
    const int bnt   = (lane >> 4) & 1;
    const int bswp  = (brow >> 2) & 1;

    float acc[4][8][4];
#pragma unroll
    for (int i = 0; i < 4; i++)
#pragma unroll
        for (int j = 0; j < 8; j++)
#pragma unroll
            for (int v = 0; v < 4; v++) acc[i][j][v] = 0.f;

    const int ntiles = K >> 4;

#pragma unroll
    for (int s = 0; s < STAGES - 1; s++) {
        const int kk = s << 4;
        const uint32_t sa = asb + s * TILE_HB;
        const uint32_t sb = bsb + s * TILE_HB;
        cpasync16(sa + off0,        aP0 + kk);
        cpasync16(sa + off0 + 2048, aP1 + kk);
        cpasync16(sb + off0,        bP0 + kk);
        cpasync16(sb + off0 + 2048, bP1 + kk);
        cp_commit();
    }

    for (int t = 0; t < ntiles; t++) {
        cp_wait<STAGES - 2>();
        __syncthreads();

        if (t + STAGES - 1 < ntiles) {
            const int s = (t + STAGES - 1) & (STAGES - 1);
            const int kk = (t + STAGES - 1) << 4;
            const uint32_t sa = asb + s * TILE_HB;
            const uint32_t sb = bsb + s * TILE_HB;
            cpasync16(sa + off0,        aP0 + kk);
            cpasync16(sa + off0 + 2048, aP1 + kk);
            cpasync16(sb + off0,        bP0 + kk);
            cpasync16(sb + off0 + 2048, bP1 + kk);
            cp_commit();
        }

        const int cur = t & (STAGES - 1);
        const uint32_t abuf = asb + cur * TILE_HB;
        const uint32_t bbuf = bsb + cur * TILE_HB;

        uint32_t afr[4][4];
#pragma unroll
        for (int i = 0; i < 4; i++) {
            int row = wr * 64 + i * 16 + lm;
            int chunk = ach ^ aswp;
            ldsm4(afr[i][0], afr[i][1], afr[i][2], afr[i][3],
                  abuf + (uint32_t)(row * 32 + chunk * 16));
        }
        uint32_t bfr[8][2];
#pragma unroll
        for (int jj = 0; jj < 4; jj++) {
            int ntile = wc * 8 + jj * 2 + bnt;
            int n = ntile * 8 + brow;
            int chunk = bch ^ bswp;
            ldsm4(bfr[2 * jj][0], bfr[2 * jj][1], bfr[2 * jj + 1][0], bfr[2 * jj + 1][1],
                  bbuf + (uint32_t)(n * 32 + chunk * 16));
        }
#pragma unroll
        for (int i = 0; i < 4; i++)
#pragma unroll
            for (int j = 0; j < 8; j++)
                mma_f16(acc[i][j], afr[i], bfr[j]);
    }

    // epilogue (fp16 output)
    const int r  = lane >> 2;
    const int cc = (lane & 3) << 1;
#pragma unroll
    for (int i = 0; i < 4; i++) {
        int row0 = bm + wr * 64 + i * 16 + r;
        int row1 = row0 + 8;
        int o0, o1;
        if (PERM == 0)      { o0 = row0;               o1 = row1; }
        else if (PERM == 1) { o0 = to_win_row(row0);   o1 = to_win_row(row1); }
        else                { o0 = from_win_row(row0); o1 = from_win_row(row1); }
#pragma unroll
        for (int j = 0; j < 8; j++) {
            int gn = bn + wc * 64 + j * 8 + cc;
            float b0 = bias[gn], b1 = bias[gn + 1];
            float v00 = acc[i][j][0] + b0, v01 = acc[i][j][1] + b1;
            float v10 = acc[i][j][2] + b0, v11 = acc[i][j][3] + b1;
            if (EPI == 1) {
                v00 = fmaxf(v00, 0.f); v01 = fmaxf(v01, 0.f);
                v10 = fmaxf(v10, 0.f); v11 = fmaxf(v11, 0.f);
            }
            *(__half2*)&C[(size_t)o0 * N + gn] = __floats2half2_rn(v00, v01);
            *(__half2*)&C[(size_t)o1 * N + gn] = __floats2half2_rn(v10, v11);
        }
    }
}

// ---------------------------------------------------------------------------
// Window attention: one block per (window, head). fp16 in/out, fp32 math.
// ---------------------------------------------------------------------------
__global__ void __launch_bounds__(256) attn_kernel(
    const __half* __restrict__ qkv, const float* __restrict__ pos_emb,
    __half* __restrict__ out)
{
    const int win = blockIdx.x;
    const int head = blockIdx.y;
    const int tid = threadIdx.x;

    __shared__ float Qt[32 * 68];
    __shared__ float Kt[32 * 68];
    __shared__ float Vs[64 * 36];
    __shared__ float Pt[64 * 68];
    __shared__ float bias_s[225];

    {
        int n  = tid >> 2;
        int c0 = (tid & 3) << 3;
        size_t base = ((size_t)win * 64 + n) * (size_t)QKV_N + head * HD_ + c0;
        {
            uint4 raw = *(const uint4*)(qkv + base);
            const __half2* h = (const __half2*)&raw;
#pragma unroll
            for (int j = 0; j < 4; j++) {
                float2 f = __half22float2(h[j]);
                Qt[(c0 + 2 * j) * 68 + n]     = f.x;
                Qt[(c0 + 2 * j + 1) * 68 + n] = f.y;
            }
        }
        {
            uint4 raw = *(const uint4*)(qkv + base + 512);
            const __half2* h = (const __half2*)&raw;
#pragma unroll
            for (int j = 0; j < 4; j++) {
                float2 f = __half22float2(h[j]);
                Kt[(c0 + 2 * j) * 68 + n]     = f.x;
                Kt[(c0 + 2 * j + 1) * 68 + n] = f.y;
            }
        }
        {
            uint4 raw = *(const uint4*)(qkv + base + 1024);
            const __half2* h = (const __half2*)&raw;
#pragma unroll
            for (int j = 0; j < 4; j++) {
                float2 f = __half22float2(h[j]);
                Vs[n * 36 + c0 + 2 * j]     = f.x;
                Vs[n * 36 + c0 + 2 * j + 1] = f.y;
            }
        }
    }
    if (tid < 225) bias_s[tid] = pos_emb[tid];
    __syncthreads();

    const int tq = tid >> 4;
    const int tk = tid & 15;

    float s[4][4];
#pragma unroll
    for (int a = 0; a < 4; a++)
#pragma unroll
        for (int b = 0; b < 4; b++) s[a][b] = 0.f;

#pragma unroll 8
    for (int d = 0; d < 32; d++) {
        float4 qf = *(const float4*)&Qt[d * 68 + tq * 4];
        float4 kf = *(const float4*)&Kt[d * 68 + tk * 4];
        const float* qa = (const float*)&qf;
        const float* ka = (const float*)&kf;
#pragma unroll
        for (int a = 0; a < 4; a++)
#pragma unroll
            for (int b = 0; b < 4; b++)
                s[a][b] = fmaf(qa[a], ka[b], s[a][b]);
    }

    const float scl = 0.17677669529663687f;
#pragma unroll
    for (int a = 0; a < 4; a++) {
        int q = tq * 4 + a, qh = q >> 3, qw = q & 7;
#pragma unroll
        for (int b = 0; b < 4; b++) {
            int k = tk * 4 + b, kh = k >> 3, kw = k & 7;
            s[a][b] = s[a][b] * scl + bias_s[(kh - qh + 7) * 15 + (kw - qw + 7)];
        }
    }

    float mx[4], sm[4];
#pragma unroll
    for (int a = 0; a < 4; a++)
        mx[a] = fmaxf(fmaxf(s[a][0], s[a][1]), fmaxf(s[a][2], s[a][3]));
#pragma unroll
    for (int off = 8; off; off >>= 1)
#pragma unroll
        for (int a = 0; a < 4; a++)
            mx[a] = fmaxf(mx[a], __shfl_xor_sync(0xffffffffu, mx[a], off));
#pragma unroll
    for (int a = 0; a < 4; a++) {
        sm[a] = 0.f;
#pragma unroll
        for (int b = 0; b < 4; b++) {
            s[a][b] = __expf(s[a][b] - mx[a]);
            sm[a] += s[a][b];
        }
    }
#pragma unroll
    for (int off = 8; off; off >>= 1)
#pragma unroll
        for (int a = 0; a < 4; a++)
            sm[a] += __shfl_xor_sync(0xffffffffu, sm[a], off);
    float inv[4];
#pragma unroll
    for (int a = 0; a < 4; a++) inv[a] = 1.f / sm[a];

#pragma unroll
    for (int b = 0; b < 4; b++) {
        float4 v = make_float4(s[0][b] * inv[0], s[1][b] * inv[1],
                               s[2][b] * inv[2], s[3][b] * inv[3]);
        *(float4*)&Pt[(tk * 4 + b) * 68 + tq * 4] = v;
    }
    __syncthreads();

    const int td = tid & 15;
    float o[4][2];
#pragma unroll
    for (int a = 0; a < 4; a++) { o[a][0] = 0.f; o[a][1] = 0.f; }
#pragma unroll 8
    for (int k = 0; k < 64; k++) {
        float4 pf = *(const float4*)&Pt[k * 68 + tq * 4];
        float2 vf = *(const float2*)&Vs[k * 36 + td * 2];
        const float* pa = (const float*)&pf;
#pragma unroll
        for (int a = 0; a < 4; a++) {
            o[a][0] = fmaf(pa[a], vf.x, o[a][0]);
            o[a][1] = fmaf(pa[a], vf.y, o[a][1]);
        }
    }
#pragma unroll
    for (int a = 0; a < 4; a++) {
        int q = tq * 4 + a;
        size_t ob = ((size_t)win * 64 + q) * (size_t)E_DIM + head * HD_ + td * 2;
        *(__half2*)&out[ob] = __floats2half2_rn(o[a][0], o[a][1]);
    }
}

// ---------------------------------------------------------------------------
// LN1: z16 = fp16( LayerNorm(x + t0h) * g + be )   (x fp32, t0h fp16)
// ---------------------------------------------------------------------------
__global__ void __launch_bounds__(128) add_ln1_kernel(
    const float* __restrict__ X, const __half* __restrict__ T,
    const float* __restrict__ g, const float* __restrict__ be,
    __half* __restrict__ z16)
{
    const int row = blockIdx.x;
    const int tid = threadIdx.x;
    size_t base = (size_t)row * E_DIM + tid * 4;

    float4 a = *(const float4*)(X + base);
    __half2 t0 = *(const __half2*)(T + base);
    __half2 t1 = *(const __half2*)(T + base + 2);
    float2 f0 = __half22float2(t0);
    float2 f1 = __half22float2(t1);
    float y0 = a.x + f0.x, y1 = a.y + f0.y, y2 = a.z + f1.x, y3 = a.w + f1.y;

    float s  = y0 + y1 + y2 + y3;
    float s2 = y0 * y0 + y1 * y1 + y2 * y2 + y3 * y3;
#pragma unroll
    for (int off = 16; off; off >>= 1) {
        s  += __shfl_down_sync(0xffffffffu, s, off);
        s2 += __shfl_down_sync(0xffffffffu, s2, off);
    }
    __shared__ float ss[4], ss2[4];
    int warp = tid >> 5, lane = tid & 31;
    if (lane == 0) { ss[warp] = s; ss2[warp] = s2; }
    __syncthreads();
    s  = ss[0] + ss[1] + ss[2] + ss[3];
    s2 = ss2[0] + ss2[1] + ss2[2] + ss2[3];

    const float rE = 1.f / 512.f;
    float mean = s * rE;
    float var  = s2 * rE - mean * mean;
    float rstd = rsqrtf(var + 1e-5f);

    int e = tid * 4;
    float4 gw = *(const float4*)(g + e);
    float4 bb = *(const float4*)(be + e);
    float o0 = (y0 - mean) * rstd * gw.x + bb.x;
    float o1 = (y1 - mean) * rstd * gw.y + bb.y;
    float o2 = (y2 - mean) * rstd * gw.z + bb.z;
    float o3 = (y3 - mean) * rstd * gw.w + bb.w;
    *(__half2*)(z16 + base)     = __floats2half2_rn(o0, o1);
    *(__half2*)(z16 + base + 2) = __floats2half2_rn(o2, o3);
}

// ---------------------------------------------------------------------------
// LN2: out = LayerNorm(z16 + t2h) * g + be   (both fp16 in, fp32 out)
// ---------------------------------------------------------------------------
__global__ void __launch_bounds__(128) add_ln2_kernel(
    const __half* __restrict__ Z, const __half* __restrict__ T,
    const float* __restrict__ g, const float* __restrict__ be,
    float* __restrict__ out)
{
    const int row = blockIdx.x;
    const int tid = threadIdx.x;
    size_t base = (size_t)row * E_DIM + tid * 4;

    __half2 z0 = *(const __half2*)(Z + base);
    __half2 z1 = *(const __half2*)(Z + base + 2);
    __half2 t0 = *(const __half2*)(T + base);
    __half2 t1 = *(const __half2*)(T + base + 2);
    float2 fz0 = __half22float2(z0), fz1 = __half22float2(z1);
    float2 ft0 = __half22float2(t0), ft1 = __half22float2(t1);
    float y0 = fz0.x + ft0.x, y1 = fz0.y + ft0.y;
    float y2 = fz1.x + ft1.x, y3 = fz1.y + ft1.y;

    float s  = y0 + y1 + y2 + y3;
    float s2 = y0 * y0 + y1 * y1 + y2 * y2 + y3 * y3;
#pragma unroll
    for (int off = 16; off; off >>= 1) {
        s  += __shfl_down_sync(0xffffffffu, s, off);
        s2 += __shfl_down_sync(0xffffffffu, s2, off);
    }
    __shared__ float ss[4], ss2[4];
    int warp = tid >> 5, lane = tid & 31;
    if (lane == 0) { ss[warp] = s; ss2[warp] = s2; }
    __syncthreads();
    s  = ss[0] + ss[1] + ss[2] + ss[3];
    s2 = ss2[0] + ss2[1] + ss2[2] + ss2[3];

    const float rE = 1.f / 512.f;
    float mean = s * rE;
    float var  = s2 * rE - mean * mean;
    float rstd = rsqrtf(var + 1e-5f);

    int e = tid * 4;
    float4 gw = *(const float4*)(g + e);
    float4 bb = *(const float4*)(be + e);
    float4 o;
    o.x = (y0 - mean) * rstd * gw.x + bb.x;
    o.y = (y1 - mean) * rstd * gw.y + bb.y;
    o.z = (y2 - mean) * rstd * gw.z + bb.z;
    o.w = (y3 - mean) * rstd * gw.w + bb.w;
    *(float4*)(out + base) = o;
}

// ---------------------------------------------------------------------------
extern "C" void kernel_launch(void* const* d_in, const int* in_sizes, int n_in,
                              void* d_out, int out_size)
{
    const float* x     = (const float*)d_in[0];
    const float* w_qkv = (const float*)d_in[1];
    const float* b_qkv = (const float*)d_in[2];
    const float* w_out = (const float*)d_in[3];
    const float* b_out = (const float*)d_in[4];
    const float* pos   = (const float*)d_in[5];
    const float* w1    = (const float*)d_in[6];
    const float* b1    = (const float*)d_in[7];
    const float* w2    = (const float*)d_in[8];
    const float* b2    = (const float*)d_in[9];
    const float* ln1w  = (const float*)d_in[10];
    const float* ln1b  = (const float*)d_in[11];
    const float* ln2w  = (const float*)d_in[12];
    const float* ln2b  = (const float*)d_in[13];
    float* out = (float*)d_out;

    static __half *p_x16 = nullptr, *p_z16 = nullptr, *p_t0h = nullptr,
                  *p_t2h = nullptr, *p_qkv16 = nullptr, *p_attn16 = nullptr,
                  *p_h16 = nullptr, *p_wqkv16 = nullptr, *p_wout16 = nullptr,
                  *p_w116 = nullptr, *p_w216 = nullptr;
    static bool inited = false;
    if (!inited) {
        cudaGetSymbolAddress((void**)&p_x16,    g_x16);
        cudaGetSymbolAddress((void**)&p_z16,    g_z16);
        cudaGetSymbolAddress((void**)&p_t0h,    g_t0h);
        cudaGetSymbolAddress((void**)&p_t2h,    g_t2h);
        cudaGetSymbolAddress((void**)&p_qkv16,  g_qkv16);
        cudaGetSymbolAddress((void**)&p_attn16, g_attn16);
        cudaGetSymbolAddress((void**)&p_h16,    g_h16);
        cudaGetSymbolAddress((void**)&p_wqkv16, g_wqkv16);
        cudaGetSymbolAddress((void**)&p_wout16, g_wout16);
        cudaGetSymbolAddress((void**)&p_w116,   g_w116);
        cudaGetSymbolAddress((void**)&p_w216,   g_w216);
        cudaFuncSetAttribute(gemm_f16<0, 1>, cudaFuncAttributeMaxDynamicSharedMemorySize, GSM_BYTES);
        cudaFuncSetAttribute(gemm_f16<0, 2>, cudaFuncAttributeMaxDynamicSharedMemorySize, GSM_BYTES);
        cudaFuncSetAttribute(gemm_f16<1, 0>, cudaFuncAttributeMaxDynamicSharedMemorySize, GSM_BYTES);
        cudaFuncSetAttribute(gemm_f16<0, 0>, cudaFuncAttributeMaxDynamicSharedMemorySize, GSM_BYTES);
        inited = true;
    }

    // 0. fp32 -> fp16 conversions (x + weights)
    {
        int n;
        n = T_TOK * E_DIM;
        cvt_f16_kernel<<<n / (256 * 4), 256>>>(x, p_x16, n);
        n = QKV_N * E_DIM;
        cvt_f16_kernel<<<n / (256 * 4), 256>>>(w_qkv, p_wqkv16, n);
        n = E_DIM * E_DIM;
        cvt_f16_kernel<<<n / (256 * 4), 256>>>(w_out, p_wout16, n);
        n = DFF_N * E_DIM;
        cvt_f16_kernel<<<n / (256 * 4), 256>>>(w1, p_w116, n);
        n = E_DIM * DFF_N;
        cvt_f16_kernel<<<n / (256 * 4), 256>>>(w2, p_w216, n);
    }

    // 1. QKV projection -> window layout
    gemm_f16<0, 1><<<dim3(QKV_N / 128, T_TOK / 128), 128, GSM_BYTES>>>(
        p_x16, p_wqkv16, b_qkv, p_qkv16, T_TOK, QKV_N, E_DIM);

    // 2. window attention
    attn_kernel<<<dim3(NWIN, NH_), 256>>>(p_qkv16, pos, p_attn16);

    // 3. output projection -> token layout (fp16)
    gemm_f16<0, 2><<<dim3(E_DIM / 128, T_TOK / 128), 128, GSM_BYTES>>>(
        p_attn16, p_wout16, b_out, p_t0h, T_TOK, E_DIM, E_DIM);

    // 4. residual + LN1 -> z16
    add_ln1_kernel<<<T_TOK, 128>>>(x, p_t0h, ln1w, ln1b, p_z16);

    // 5. FFN up + ReLU
    gemm_f16<1, 0><<<dim3(DFF_N / 128, T_TOK / 128), 128, GSM_BYTES>>>(
        p_z16, p_w116, b1, p_h16, T_TOK, DFF_N, E_DIM);

    // 6. FFN down (fp16)
    gemm_f16<0, 0><<<dim3(E_DIM / 128, T_TOK / 128), 128, GSM_BYTES>>>(
        p_h16, p_w216, b2, p_t2h, T_TOK, E_DIM, DFF_N);

    // 7. residual + LN2 -> final fp32 output
    add_ln2_kernel<<<T_TOK, 128>>>(p_z16, p_t2h, ln2w, ln2b, out);
}